// round 5
// baseline (speedup 1.0000x reference)
#include <cuda_runtime.h>
#include <cstdint>
#include <math.h>

typedef unsigned long long ull;

__device__ __forceinline__ ull fma2(ull a, ull b, ull c) {
    ull d; asm("fma.rn.f32x2 %0, %1, %2, %3;" : "=l"(d) : "l"(a), "l"(b), "l"(c)); return d;
}
__device__ __forceinline__ ull pk(float lo, float hi) {
    ull d; asm("mov.b64 %0, {%1, %2};" : "=l"(d) : "f"(lo), "f"(hi)); return d;
}
__device__ __forceinline__ void upk(ull v, float& lo, float& hi) {
    asm("mov.b64 {%0, %1}, %2;" : "=f"(lo), "=f"(hi) : "l"(v));
}

// ---------------- Phase A: xw = x @ W + b, written into d_out --------------
// dir 0 -> out[b][t][j],  dir 1 -> out[b][511-t][512+j]
__global__ __launch_bounds__(256) void input_proj_kernel(
    const float* __restrict__ x,
    const float* __restrict__ Wf, const float* __restrict__ bf,
    const float* __restrict__ Wb, const float* __restrict__ bb,
    float* __restrict__ out)
{
    const int dir = blockIdx.z;
    const float* __restrict__ W = dir ? Wb : Wf;
    const float* __restrict__ bias = dir ? bb : bf;
    const int mBlk = blockIdx.x * 64;
    const int nBlk = blockIdx.y * 64;
    const int tid = threadIdx.x;

    __shared__ __align__(16) float As[16][72];
    __shared__ __align__(16) float Bs[16][72];

    const int ar = tid >> 2, ac = (tid & 3) * 4;
    const int br = tid >> 4, bc = (tid & 15) * 4;
    const int tm = (tid >> 4) * 4, tn = (tid & 15) * 4;

    float acc[4][4];
#pragma unroll
    for (int i = 0; i < 4; i++)
#pragma unroll
        for (int j = 0; j < 4; j++) acc[i][j] = 0.f;

    const float* aptr = x + (size_t)(mBlk + ar) * 512 + ac;
    const float* bptr = W + (size_t)br * 512 + nBlk + bc;

    for (int kk = 0; kk < 512; kk += 16) {
        const float4 av = *(const float4*)(aptr + kk);
        const float4 bv = *(const float4*)(bptr + (size_t)kk * 512);
        __syncthreads();
        As[ac + 0][ar] = av.x; As[ac + 1][ar] = av.y;
        As[ac + 2][ar] = av.z; As[ac + 3][ar] = av.w;
        *(float4*)&Bs[br][bc] = bv;
        __syncthreads();
#pragma unroll
        for (int k = 0; k < 16; k++) {
            float am[4], bn[4];
            *(float4*)am = *(const float4*)&As[k][tm];
            *(float4*)bn = *(const float4*)&Bs[k][tn];
#pragma unroll
            for (int i = 0; i < 4; i++)
#pragma unroll
                for (int j = 0; j < 4; j++)
                    acc[i][j] = fmaf(am[i], bn[j], acc[i][j]);
        }
    }

    float bo[4];
#pragma unroll
    for (int j = 0; j < 4; j++) bo[j] = bias[nBlk + tn + j];

#pragma unroll
    for (int i = 0; i < 4; i++) {
        const int m = mBlk + tm + i;     // m = b*512 + t
        const int b = m >> 9, t = m & 511;
        size_t addr;
        if (dir == 0) addr = (size_t)m * 1024 + (nBlk + tn);
        else          addr = ((size_t)(b << 9) + (511 - t)) * 1024 + 512 + (nBlk + tn);
        float4 v;
        v.x = acc[i][0] + bo[0]; v.y = acc[i][1] + bo[1];
        v.z = acc[i][2] + bo[2]; v.w = acc[i][3] + bo[3];
        *(float4*)(out + addr) = v;
    }
}

// ---------------- Phase B: recurrent scan, in place on d_out ---------------
// 32 CTAs: (dir, 4 batch rows). h duplicated as f32x2 pairs in smem,
// double buffered; U streamed from L2 each step; 1 syncthreads/step.
__global__ __launch_bounds__(128) void scan_kernel(
    const float* __restrict__ Uf, const float* __restrict__ Ub,
    float* __restrict__ out)
{
    const int dir = blockIdx.x >> 4;
    const int b0 = (blockIdx.x & 15) * 4;
    const float* __restrict__ U = dir ? Ub : Uf;
    const int off = dir << 9;
    const int tid = threadIdx.x;
    const int j0 = tid * 4;

    __shared__ __align__(16) ull h2[2][4][512];   // 32 KB, (h,h) pairs

#pragma unroll
    for (int r = 0; r < 4; r++)
#pragma unroll
        for (int i = 0; i < 4; i++) h2[0][r][j0 + i] = 0ull;
    __syncthreads();

    float* base[4];
#pragma unroll
    for (int r = 0; r < 4; r++)
        base[r] = out + ((size_t)(b0 + r) << 9) * 1024 + off + j0;

    int p = 0;
    for (int s = 0; s < 512; s++) {
        ull a0[4], a1[4];
#pragma unroll
        for (int r = 0; r < 4; r++) {
            float4 xv = *(const float4*)(base[r] + (size_t)s * 1024);
            a0[r] = pk(xv.x, xv.y);
            a1[r] = pk(xv.z, xv.w);
        }
        const float* up = U + j0;
        for (int kk = 0; kk < 512; kk += 4) {
#pragma unroll
            for (int q = 0; q < 4; q++) {
                float4 u = *(const float4*)(up + (size_t)(kk + q) * 512);
                ull u01 = pk(u.x, u.y), u23 = pk(u.z, u.w);
#pragma unroll
                for (int r = 0; r < 4; r++) {
                    ull hh = h2[p][r][kk + q];
                    a0[r] = fma2(hh, u01, a0[r]);
                    a1[r] = fma2(hh, u23, a1[r]);
                }
            }
        }
        const int np = p ^ 1;
#pragma unroll
        for (int r = 0; r < 4; r++) {
            float y0, y1, y2, y3;
            upk(a0[r], y0, y1); upk(a1[r], y2, y3);
            y0 = tanhf(y0); y1 = tanhf(y1); y2 = tanhf(y2); y3 = tanhf(y3);
            float4 w; w.x = y0; w.y = y1; w.z = y2; w.w = y3;
            *(float4*)(base[r] + (size_t)s * 1024) = w;
            h2[np][r][j0 + 0] = pk(y0, y0);
            h2[np][r][j0 + 1] = pk(y1, y1);
            h2[np][r][j0 + 2] = pk(y2, y2);
            h2[np][r][j0 + 3] = pk(y3, y3);
        }
        __syncthreads();
        p = np;
    }
}

extern "C" void kernel_launch(void* const* d_in, const int* in_sizes, int n_in,
                              void* d_out, int out_size) {
    const float* x  = (const float*)d_in[0];
    const float* Wf = (const float*)d_in[1];
    const float* Uf = (const float*)d_in[2];
    const float* bf = (const float*)d_in[3];
    const float* Wb = (const float*)d_in[4];
    const float* Ub = (const float*)d_in[5];
    const float* bb = (const float*)d_in[6];
    float* out = (float*)d_out;
    (void)in_sizes; (void)n_in; (void)out_size;

    dim3 gA(512, 8, 2);
    input_proj_kernel<<<gA, 256>>>(x, Wf, bf, Wb, bb, out);
    scan_kernel<<<32, 128>>>(Uf, Ub, out);
}

// round 7
// speedup vs baseline: 1.4477x; 1.4477x over previous
#include <cuda_runtime.h>
#include <cstdint>
#include <math.h>

typedef unsigned long long ull;

__device__ __forceinline__ ull fma2(ull a, ull b, ull c) { ull d; asm("fma.rn.f32x2 %0,%1,%2,%3;":"=l"(d):"l"(a),"l"(b),"l"(c)); return d; }
__device__ __forceinline__ ull add2(ull a, ull b) { ull d; asm("add.rn.f32x2 %0,%1,%2;":"=l"(d):"l"(a),"l"(b)); return d; }
__device__ __forceinline__ ull pk(float lo, float hi) { ull d; asm("mov.b64 %0,{%1,%2};":"=l"(d):"f"(lo),"f"(hi)); return d; }
__device__ __forceinline__ void upk(ull v, float& lo, float& hi) { asm("mov.b64 {%0,%1},%2;":"=f"(lo),"=f"(hi):"l"(v)); }
__device__ __forceinline__ unsigned s2u(const void* p){ unsigned r; asm("{.reg .u64 t; cvta.to.shared.u64 t, %1; cvt.u32.u64 %0, t;}":"=r"(r):"l"(p)); return r; }
__device__ __forceinline__ unsigned mapa_r(unsigned a, unsigned r){ unsigned o; asm("mapa.shared::cluster.u32 %0,%1,%2;":"=r"(o):"r"(a),"r"(r)); return o; }
__device__ __forceinline__ void stc64(unsigned a, ull v){ asm volatile("st.shared::cluster.u64 [%0], %1;"::"r"(a),"l"(v):"memory"); }
__device__ __forceinline__ unsigned ctarank(){ unsigned r; asm("mov.u32 %0, %%cluster_ctarank;":"=r"(r)); return r; }
__device__ __forceinline__ void csync(){
    asm volatile("barrier.cluster.arrive.aligned;":::"memory");
    asm volatile("barrier.cluster.wait.aligned;":::"memory");
}

// ---------------- Phase A: xw = x @ W + b, written into d_out --------------
__global__ __launch_bounds__(256) void input_proj_kernel(
    const float* __restrict__ x,
    const float* __restrict__ Wf, const float* __restrict__ bf,
    const float* __restrict__ Wb, const float* __restrict__ bb,
    float* __restrict__ out)
{
    const int dir = blockIdx.z;
    const float* __restrict__ W = dir ? Wb : Wf;
    const float* __restrict__ bias = dir ? bb : bf;
    const int mBlk = blockIdx.x * 64;
    const int nBlk = blockIdx.y * 64;
    const int tid = threadIdx.x;

    __shared__ __align__(16) float As[16][72];
    __shared__ __align__(16) float Bs[16][72];

    const int ar = tid >> 2, ac = (tid & 3) * 4;
    const int br = tid >> 4, bc = (tid & 15) * 4;
    const int tm = (tid >> 4) * 4, tn = (tid & 15) * 4;

    float acc[4][4];
#pragma unroll
    for (int i = 0; i < 4; i++)
#pragma unroll
        for (int j = 0; j < 4; j++) acc[i][j] = 0.f;

    const float* aptr = x + (size_t)(mBlk + ar) * 512 + ac;
    const float* bptr = W + (size_t)br * 512 + nBlk + bc;

    for (int kk = 0; kk < 512; kk += 16) {
        const float4 av = *(const float4*)(aptr + kk);
        const float4 bv = *(const float4*)(bptr + (size_t)kk * 512);
        __syncthreads();
        As[ac + 0][ar] = av.x; As[ac + 1][ar] = av.y;
        As[ac + 2][ar] = av.z; As[ac + 3][ar] = av.w;
        *(float4*)&Bs[br][bc] = bv;
        __syncthreads();
#pragma unroll
        for (int k = 0; k < 16; k++) {
            float am[4], bn[4];
            *(float4*)am = *(const float4*)&As[k][tm];
            *(float4*)bn = *(const float4*)&Bs[k][tn];
#pragma unroll
            for (int i = 0; i < 4; i++)
#pragma unroll
                for (int j = 0; j < 4; j++)
                    acc[i][j] = fmaf(am[i], bn[j], acc[i][j]);
        }
    }

    float bo[4];
#pragma unroll
    for (int j = 0; j < 4; j++) bo[j] = bias[nBlk + tn + j];

#pragma unroll
    for (int i = 0; i < 4; i++) {
        const int m = mBlk + tm + i;
        const int b = m >> 9, t = m & 511;
        size_t addr;
        if (dir == 0) addr = (size_t)m * 1024 + (nBlk + tn);
        else          addr = ((size_t)(b << 9) + (511 - t)) * 1024 + 512 + (nBlk + tn);
        float4 v;
        v.x = acc[i][0] + bo[0]; v.y = acc[i][1] + bo[1];
        v.z = acc[i][2] + bo[2]; v.w = acc[i][3] + bo[3];
        *(float4*)(out + addr) = v;
    }
}

// ---------------- Phase B: cluster scan, U resident in SMEM ----------------
// 16 clusters x 8 CTAs. Cluster = (dir, 8 batch rows). CTA rank owns
// U[:, rank*64 .. +64) in smem. h double-buffered as dup f32x2 pairs,
// layout [buf][k][row], replicated to all 8 CTAs via st.shared::cluster.
#define SM_U   0
#define SM_H   131072            // ull h2[2][512][8]  = 65536 B
#define SM_RED 196608            // ull red[8][16][8][2] = 16384 B
#define SM_TOT 212992

__global__ void __cluster_dims__(8,1,1) __launch_bounds__(128,1)
scan_kernel(const float* __restrict__ Uf, const float* __restrict__ Ub,
            float* __restrict__ out)
{
    extern __shared__ __align__(16) char smem[];
    float* Usm = (float*)(smem + SM_U);           // [512][64]
    ull*   h2  = (ull*)(smem + SM_H);             // [2][512][8]
    ull*   red = (ull*)(smem + SM_RED);           // [8][16][8][2]

    const unsigned rank = ctarank();
    const int cid = blockIdx.x >> 3;
    const int dir = cid >> 3;
    const int b0  = (cid & 7) * 8;
    const float* __restrict__ U = dir ? Ub : Uf;
    const int tid = threadIdx.x;

    // load own U slice (once)
    for (int i = tid; i < 512 * 16; i += 128) {
        int k = i >> 4, c4 = i & 15;
        *(float4*)&Usm[k * 64 + c4 * 4] =
            *(const float4*)&U[(size_t)k * 512 + rank * 64 + c4 * 4];
    }
    for (int i = tid; i < 512 * 8; i += 128) h2[i] = 0ull;

    const int cg = tid & 15;     // 4-col group within slice
    const int kc = tid >> 4;     // k chunk (64 ks)        [compute role]
    const int rcg = tid & 15;    // reduce: col group
    const int rrow = tid >> 4;   // reduce: batch row      [reduce role]
    const int jglob = rank * 64 + rcg * 4;

    unsigned sbase = s2u(smem);
    unsigned rb[8];
#pragma unroll
    for (int r = 0; r < 8; r++) rb[r] = mapa_r(sbase, r);

    float* xwp = out + ((size_t)(b0 + rrow) << 9) * 1024 + (dir << 9) + jglob;

    csync();   // U + h0 visible cluster-wide

    int p = 0;
    for (int s = 0; s < 512; s++) {
        // partial matvec over this thread's k-chunk, all 8 rows, 4 cols
        ull a0[8], a1[8];
#pragma unroll
        for (int r = 0; r < 8; r++) { a0[r] = 0ull; a1[r] = 0ull; }
        const ull* hc = h2 + p * 4096;
#pragma unroll 4
        for (int kq = 0; kq < 64; kq++) {
            const int k = kc * 64 + kq;
            float4 u = *(const float4*)&Usm[k * 64 + cg * 4];
            ull u01 = pk(u.x, u.y), u23 = pk(u.z, u.w);
            const ull* hr = hc + k * 8;
            ull hp[8];
#pragma unroll
            for (int q = 0; q < 4; q++)
                *(uint4*)&hp[q * 2] = *(const uint4*)&hr[q * 2];
#pragma unroll
            for (int r = 0; r < 8; r++) {
                a0[r] = fma2(hp[r], u01, a0[r]);
                a1[r] = fma2(hp[r], u23, a1[r]);
            }
        }
        // stash partials
        ull* rp = &red[((kc * 16 + cg) * 8) * 2];
#pragma unroll
        for (int r = 0; r < 8; r++) { rp[r * 2] = a0[r]; rp[r * 2 + 1] = a1[r]; }
        __syncthreads();

        // reduce: thread (rcg, rrow) -> 4 output cols of one row
        ull s0 = 0ull, s1 = 0ull;
#pragma unroll
        for (int q = 0; q < 8; q++) {
            const ull* qp = &red[((q * 16 + rcg) * 8 + rrow) * 2];
            s0 = add2(s0, qp[0]); s1 = add2(s1, qp[1]);
        }
        float4 xv = *(const float4*)(xwp + (size_t)s * 1024);
        float t0, t1, y0, y1, y2, y3;
        upk(s0, t0, t1); y0 = tanhf(xv.x + t0); y1 = tanhf(xv.y + t1);
        upk(s1, t0, t1); y2 = tanhf(xv.z + t0); y3 = tanhf(xv.w + t1);
        float4 w; w.x = y0; w.y = y1; w.z = y2; w.w = y3;
        *(float4*)(xwp + (size_t)s * 1024) = w;

        ull hv0 = pk(y0, y0), hv1 = pk(y1, y1), hv2 = pk(y2, y2), hv3 = pk(y3, y3);
        const int np = p ^ 1;
        const unsigned hoff = (unsigned)SM_H + (unsigned)(np * 4096 + rrow) * 8u
                              + (unsigned)jglob * 64u;
#pragma unroll
        for (int r8 = 0; r8 < 8; r8++) {
            unsigned base = rb[r8] + hoff;
            stc64(base,        hv0);
            stc64(base + 64u,  hv1);
            stc64(base + 128u, hv2);
            stc64(base + 192u, hv3);
        }
        csync();
        p = np;
    }
}

extern "C" void kernel_launch(void* const* d_in, const int* in_sizes, int n_in,
                              void* d_out, int out_size) {
    const float* x  = (const float*)d_in[0];
    const float* Wf = (const float*)d_in[1];
    const float* Uf = (const float*)d_in[2];
    const float* bf = (const float*)d_in[3];
    const float* Wb = (const float*)d_in[4];
    const float* Ub = (const float*)d_in[5];
    const float* bb = (const float*)d_in[6];
    float* out = (float*)d_out;
    (void)in_sizes; (void)n_in; (void)out_size;

    dim3 gA(512, 8, 2);
    input_proj_kernel<<<gA, 256>>>(x, Wf, bf, Wb, bb, out);

    cudaFuncSetAttribute(scan_kernel,
                         cudaFuncAttributeMaxDynamicSharedMemorySize, SM_TOT);
    scan_kernel<<<128, 128, SM_TOT>>>(Uf, Ub, out);
}

// round 8
// speedup vs baseline: 2.7919x; 1.9286x over previous
#include <cuda_runtime.h>
#include <cstdint>
#include <math.h>

typedef unsigned long long ull;

__device__ __forceinline__ ull fma2(ull a, ull b, ull c) { ull d; asm("fma.rn.f32x2 %0,%1,%2,%3;":"=l"(d):"l"(a),"l"(b),"l"(c)); return d; }
__device__ __forceinline__ ull pk(float lo, float hi) { ull d; asm("mov.b64 %0,{%1,%2};":"=l"(d):"f"(lo),"f"(hi)); return d; }
__device__ __forceinline__ void upk(ull v, float& lo, float& hi) { asm("mov.b64 {%0,%1},%2;":"=f"(lo),"=f"(hi):"l"(v)); }
__device__ __forceinline__ unsigned s2u(const void* p){ unsigned r; asm("{.reg .u64 t; cvta.to.shared.u64 t, %1; cvt.u32.u64 %0, t;}":"=r"(r):"l"(p)); return r; }
__device__ __forceinline__ unsigned mapa_r(unsigned a, unsigned r){ unsigned o; asm("mapa.shared::cluster.u32 %0,%1,%2;":"=r"(o):"r"(a),"r"(r)); return o; }
__device__ __forceinline__ void stc64(unsigned a, ull v){ asm volatile("st.shared::cluster.u64 [%0], %1;"::"r"(a),"l"(v):"memory"); }
__device__ __forceinline__ unsigned ctarank(){ unsigned r; asm("mov.u32 %0, %%cluster_ctarank;":"=r"(r)); return r; }
__device__ __forceinline__ void csync(){
    asm volatile("barrier.cluster.arrive.aligned;":::"memory");
    asm volatile("barrier.cluster.wait.aligned;":::"memory");
}

// ---------------- Phase A: xw = x @ W + b, written into d_out --------------
// dir 0 -> out[b][t][j],  dir 1 -> out[b][511-t][512+j]
__global__ __launch_bounds__(256) void input_proj_kernel(
    const float* __restrict__ x,
    const float* __restrict__ Wf, const float* __restrict__ bf,
    const float* __restrict__ Wb, const float* __restrict__ bb,
    float* __restrict__ out)
{
    const int dir = blockIdx.z;
    const float* __restrict__ W = dir ? Wb : Wf;
    const float* __restrict__ bias = dir ? bb : bf;
    const int mBlk = blockIdx.x * 64;
    const int nBlk = blockIdx.y * 64;
    const int tid = threadIdx.x;

    __shared__ __align__(16) float As[16][72];
    __shared__ __align__(16) float Bs[16][72];

    const int ar = tid >> 2, ac = (tid & 3) * 4;
    const int br = tid >> 4, bc = (tid & 15) * 4;
    const int tm = (tid >> 4) * 4, tn = (tid & 15) * 4;

    float acc[4][4];
#pragma unroll
    for (int i = 0; i < 4; i++)
#pragma unroll
        for (int j = 0; j < 4; j++) acc[i][j] = 0.f;

    const float* aptr = x + (size_t)(mBlk + ar) * 512 + ac;
    const float* bptr = W + (size_t)br * 512 + nBlk + bc;

    for (int kk = 0; kk < 512; kk += 16) {
        const float4 av = *(const float4*)(aptr + kk);
        const float4 bv = *(const float4*)(bptr + (size_t)kk * 512);
        __syncthreads();
        As[ac + 0][ar] = av.x; As[ac + 1][ar] = av.y;
        As[ac + 2][ar] = av.z; As[ac + 3][ar] = av.w;
        *(float4*)&Bs[br][bc] = bv;
        __syncthreads();
#pragma unroll
        for (int k = 0; k < 16; k++) {
            float am[4], bn[4];
            *(float4*)am = *(const float4*)&As[k][tm];
            *(float4*)bn = *(const float4*)&Bs[k][tn];
#pragma unroll
            for (int i = 0; i < 4; i++)
#pragma unroll
                for (int j = 0; j < 4; j++)
                    acc[i][j] = fmaf(am[i], bn[j], acc[i][j]);
        }
    }

    float bo[4];
#pragma unroll
    for (int j = 0; j < 4; j++) bo[j] = bias[nBlk + tn + j];

#pragma unroll
    for (int i = 0; i < 4; i++) {
        const int m = mBlk + tm + i;
        const int b = m >> 9, t = m & 511;
        size_t addr;
        if (dir == 0) addr = (size_t)m * 1024 + (nBlk + tn);
        else          addr = ((size_t)(b << 9) + (511 - t)) * 1024 + 512 + (nBlk + tn);
        float4 v;
        v.x = acc[i][0] + bo[0]; v.y = acc[i][1] + bo[1];
        v.z = acc[i][2] + bo[2]; v.w = acc[i][3] + bo[3];
        *(float4*)(out + addr) = v;
    }
}

// ---------------- Phase B: k-sliced cluster scan ---------------------------
// 16 clusters x 8 CTAs x 256 thr. Cluster = (dir, 8 batch rows).
// CTA rank owns U rows [64r,64r+64) (k-slice), packed as k-pairs P[kp][col],
// and h slice cols [64r,64r+64) as pairs h2[kp][row]. Matvec over own k uses
// only own h. Partials (8x512 f32) pushed to col-owner peers (warp w -> rank
// w), reduced there with xw + tanh. Double-buffered partials, 1 csync/step.
#define SM_P   0                  // ull P[32][512]      = 131072 B
#define SM_H   131072             // ull h2[32][8]       = 2048 B
#define SM_RED 133120             // float red[2][8][8][64] = 32768 B
#define SM_TOT 165888

__global__ void __cluster_dims__(8,1,1) __launch_bounds__(256,1)
scan_kernel(const float* __restrict__ Uf, const float* __restrict__ Ub,
            float* __restrict__ out)
{
    extern __shared__ __align__(16) char smem[];
    ull*   P   = (ull*)(smem + SM_P);
    ull*   h2  = (ull*)(smem + SM_H);
    float* red = (float*)(smem + SM_RED);

    const unsigned rank = ctarank();
    const int cid = blockIdx.x >> 3;
    const int dir = cid >> 3;
    const int b0  = (cid & 7) * 8;
    const float* __restrict__ U = dir ? Ub : Uf;
    const int tid = threadIdx.x;
    const int k0 = rank * 64;

    // one-time: pack own U k-slice as k-pairs, [kp][col]
    for (int i = tid; i < 32 * 512; i += 256) {
        const int kp = i >> 9, j = i & 511;
        const float u0 = U[(size_t)(k0 + 2 * kp) * 512 + j];
        const float u1 = U[(size_t)(k0 + 2 * kp + 1) * 512 + j];
        P[kp * 512 + j] = pk(u0, u1);
    }
    h2[tid] = 0ull;                       // 32*8 = 256 entries

    // compute role: cols c0=2t, c0+1 over all 512; peer = warp id
    const int c0 = 2 * tid;
    const unsigned peer = (unsigned)(tid >> 5);
    const unsigned pb = mapa_r(s2u(smem) + (unsigned)SM_RED, peer);

    // reduce role: row rr, local col pair lc
    const int rr = tid >> 5;
    const int lc = (tid & 31) * 2;
    const int jglob = (int)rank * 64 + lc;
    float* xwp = out + (((size_t)(b0 + rr) << 9)) * 1024 + (size_t)(dir << 9) + jglob;
    const int hidx = (tid & 31) * 8 + rr;

    csync();   // init visible cluster-wide before any remote push

    int buf = 0;
    for (int s = 0; s < 512; s++) {
        const float2 xv = *(const float2*)(xwp + (size_t)s * 1024);  // prefetch

        ull acc0[8], acc1[8];
#pragma unroll
        for (int r = 0; r < 8; r++) { acc0[r] = 0ull; acc1[r] = 0ull; }

#pragma unroll 4
        for (int kp = 0; kp < 32; kp++) {
            ull hp[8];
#pragma unroll
            for (int q = 0; q < 4; q++)
                *(uint4*)&hp[q * 2] = *(const uint4*)&h2[kp * 8 + q * 2];
            ull uu[2];
            *(uint4*)uu = *(const uint4*)&P[kp * 512 + c0];
#pragma unroll
            for (int r = 0; r < 8; r++) {
                acc0[r] = fma2(hp[r], uu[0], acc0[r]);
                acc1[r] = fma2(hp[r], uu[1], acc1[r]);
            }
        }

        // push partials to col-owner peer: red[buf][src=rank][r][c0&63]
        const unsigned dst = pb + (unsigned)(buf * 16384 + (int)rank * 2048 + (c0 & 63) * 4);
#pragma unroll
        for (int r = 0; r < 8; r++) {
            float a, b, p0, p1;
            upk(acc0[r], a, b); p0 = a + b;
            upk(acc1[r], a, b); p1 = a + b;
            stc64(dst + (unsigned)(r * 256), pk(p0, p1));
        }
        csync();

        // reduce own slice: sum 8 srcs + xw, tanh
        const float* rp = red + buf * 4096 + rr * 64 + lc;
        float s0 = xv.x, s1 = xv.y;
#pragma unroll
        for (int q = 0; q < 8; q++) {
            const float2 v = *(const float2*)(rp + q * 512);
            s0 += v.x; s1 += v.y;
        }
        const float y0 = tanhf(s0), y1 = tanhf(s1);
        float2 w; w.x = y0; w.y = y1;
        *(float2*)(xwp + (size_t)s * 1024) = w;
        h2[hidx] = pk(y0, y1);
        __syncthreads();
        buf ^= 1;
    }
}

extern "C" void kernel_launch(void* const* d_in, const int* in_sizes, int n_in,
                              void* d_out, int out_size) {
    const float* x  = (const float*)d_in[0];
    const float* Wf = (const float*)d_in[1];
    const float* Uf = (const float*)d_in[2];
    const float* bf = (const float*)d_in[3];
    const float* Wb = (const float*)d_in[4];
    const float* Ub = (const float*)d_in[5];
    const float* bb = (const float*)d_in[6];
    float* out = (float*)d_out;
    (void)in_sizes; (void)n_in; (void)out_size;

    dim3 gA(512, 8, 2);
    input_proj_kernel<<<gA, 256>>>(x, Wf, bf, Wb, bb, out);

    cudaFuncSetAttribute(scan_kernel,
                         cudaFuncAttributeMaxDynamicSharedMemorySize, SM_TOT);
    scan_kernel<<<128, 256, SM_TOT>>>(Uf, Ub, out);
}

// round 9
// speedup vs baseline: 2.8131x; 1.0076x over previous
#include <cuda_runtime.h>
#include <cstdint>
#include <math.h>

typedef unsigned long long ull;

__device__ __forceinline__ ull fma2(ull a, ull b, ull c) { ull d; asm("fma.rn.f32x2 %0,%1,%2,%3;":"=l"(d):"l"(a),"l"(b),"l"(c)); return d; }
__device__ __forceinline__ ull pk(float lo, float hi) { ull d; asm("mov.b64 %0,{%1,%2};":"=l"(d):"f"(lo),"f"(hi)); return d; }
__device__ __forceinline__ void upk(ull v, float& lo, float& hi) { asm("mov.b64 {%0,%1},%2;":"=f"(lo),"=f"(hi):"l"(v)); }
__device__ __forceinline__ unsigned s2u(const void* p){ unsigned r; asm("{.reg .u64 t; cvta.to.shared.u64 t, %1; cvt.u32.u64 %0, t;}":"=r"(r):"l"(p)); return r; }
__device__ __forceinline__ unsigned mapa_r(unsigned a, unsigned r){ unsigned o; asm("mapa.shared::cluster.u32 %0,%1,%2;":"=r"(o):"r"(a),"r"(r)); return o; }
__device__ __forceinline__ unsigned ctarank(){ unsigned r; asm("mov.u32 %0, %%cluster_ctarank;":"=r"(r)); return r; }
__device__ __forceinline__ void csync(){
    asm volatile("barrier.cluster.arrive.aligned;":::"memory");
    asm volatile("barrier.cluster.wait.aligned;":::"memory");
}
__device__ __forceinline__ void st_async64(unsigned dst, ull v, unsigned mbar){
    asm volatile("st.async.shared::cluster.mbarrier::complete_tx::bytes.b64 [%0], %1, [%2];"
        :: "r"(dst), "l"(v), "r"(mbar) : "memory");
}
__device__ __forceinline__ void bar_init(unsigned bar, unsigned cnt){
    asm volatile("mbarrier.init.shared.b64 [%0], %1;" :: "r"(bar), "r"(cnt) : "memory");
}
__device__ __forceinline__ void bar_expect(unsigned bar, unsigned bytes){
    asm volatile("mbarrier.arrive.expect_tx.shared.b64 _, [%0], %1;" :: "r"(bar), "r"(bytes) : "memory");
}
__device__ __forceinline__ void bar_wait(unsigned bar, unsigned phase){
    unsigned done;
    asm volatile("{\n\t.reg .pred p;\n\t"
        "mbarrier.try_wait.parity.acquire.cta.shared::cta.b64 p, [%1], %2;\n\t"
        "selp.b32 %0, 1, 0, p;\n\t}"
        : "=r"(done) : "r"(bar), "r"(phase) : "memory");
    if (!done) {
        asm volatile("{\n\t.reg .pred P1;\n\t"
            "W_%=:\n\t"
            "mbarrier.try_wait.parity.acquire.cta.shared::cta.b64 P1, [%0], %1, 0x989680;\n\t"
            "@P1 bra.uni D_%=;\n\t"
            "bra.uni W_%=;\n\t"
            "D_%=:\n\t}"
            :: "r"(bar), "r"(phase) : "memory");
    }
}
__device__ __forceinline__ float tanh_fast(float x){
    float e, r;
    asm("ex2.approx.f32 %0, %1;" : "=f"(e) : "f"(x * 2.885390081777927f)); // e^(2x)
    asm("rcp.approx.f32 %0, %1;" : "=f"(r) : "f"(e + 1.0f));
    return fmaf(-2.0f, r, 1.0f);
}

// ---------------- Phase A: xw = x @ W + b (f32x2, 128x128 tiles) -----------
// dir 0 -> out[b][t][j],  dir 1 -> out[b][511-t][512+j]
__global__ __launch_bounds__(256,2) void input_proj_kernel(
    const float* __restrict__ x,
    const float* __restrict__ Wf, const float* __restrict__ bf,
    const float* __restrict__ Wb, const float* __restrict__ bb,
    float* __restrict__ out)
{
    const int dir = blockIdx.z;
    const float* __restrict__ W = dir ? Wb : Wf;
    const float* __restrict__ bias = dir ? bb : bf;
    const int mBlk = blockIdx.x * 128;
    const int nBlk = blockIdx.y * 128;
    const int tid = threadIdx.x;

    __shared__ __align__(16) ull   As2[16][128];   // dup (a,a) pairs, 16 KB
    __shared__ __align__(16) float Bs[16][132];

    const int ar = tid >> 1, ac = (tid & 1) * 8;       // A: row, k-group
    const int brow = tid >> 5, bcol = (tid & 31) * 4;  // B: k-row, col
    const int tm = (tid >> 4) * 8, tn = (tid & 15) * 8;

    ull acc[8][4];
#pragma unroll
    for (int i = 0; i < 8; i++)
#pragma unroll
        for (int j = 0; j < 4; j++) acc[i][j] = 0ull;

    const float* aptr = x + (size_t)(mBlk + ar) * 512 + ac;
    const float* bptr = W + (size_t)brow * 512 + nBlk + bcol;

    for (int kk = 0; kk < 512; kk += 16) {
        const float4 av0 = *(const float4*)(aptr + kk);
        const float4 av1 = *(const float4*)(aptr + kk + 4);
        const float4 bv0 = *(const float4*)(bptr + (size_t)kk * 512);
        const float4 bv1 = *(const float4*)(bptr + (size_t)(kk + 8) * 512);
        __syncthreads();
        As2[ac + 0][ar] = pk(av0.x, av0.x);
        As2[ac + 1][ar] = pk(av0.y, av0.y);
        As2[ac + 2][ar] = pk(av0.z, av0.z);
        As2[ac + 3][ar] = pk(av0.w, av0.w);
        As2[ac + 4][ar] = pk(av1.x, av1.x);
        As2[ac + 5][ar] = pk(av1.y, av1.y);
        As2[ac + 6][ar] = pk(av1.z, av1.z);
        As2[ac + 7][ar] = pk(av1.w, av1.w);
        *(float4*)&Bs[brow][bcol]     = bv0;
        *(float4*)&Bs[brow + 8][bcol] = bv1;
        __syncthreads();
#pragma unroll
        for (int k = 0; k < 16; k++) {
            ull a2[8], b2[4];
#pragma unroll
            for (int u = 0; u < 4; u++)
                *(uint4*)&a2[u * 2] = *(const uint4*)&As2[k][tm + u * 2];
            *(uint4*)&b2[0] = *(const uint4*)&Bs[k][tn];
            *(uint4*)&b2[2] = *(const uint4*)&Bs[k][tn + 4];
#pragma unroll
            for (int i = 0; i < 8; i++)
#pragma unroll
                for (int j = 0; j < 4; j++)
                    acc[i][j] = fma2(a2[i], b2[j], acc[i][j]);
        }
    }

    float bo[8];
#pragma unroll
    for (int j = 0; j < 8; j++) bo[j] = bias[nBlk + tn + j];

#pragma unroll
    for (int i = 0; i < 8; i++) {
        const int m = mBlk + tm + i;
        const int b = m >> 9, t = m & 511;
        size_t addr;
        if (dir == 0) addr = (size_t)m * 1024 + (nBlk + tn);
        else          addr = ((size_t)(b << 9) + (511 - t)) * 1024 + 512 + (nBlk + tn);
        float v[8];
#pragma unroll
        for (int j = 0; j < 4; j++) {
            float lo, hi; upk(acc[i][j], lo, hi);
            v[2 * j] = lo + bo[2 * j]; v[2 * j + 1] = hi + bo[2 * j + 1];
        }
        *(float4*)(out + addr)     = *(float4*)&v[0];
        *(float4*)(out + addr + 4) = *(float4*)&v[4];
    }
}

// ---------------- Phase B: k-sliced cluster scan, st.async sync ------------
// 16 clusters x 8 CTAs x 256 thr. CTA rank owns U rows [64r,64r+64) packed as
// k-pairs P[kp][col]; own h slice (cols [64r,64r+64)) double-buffered as pairs
// h2[buf][kp][row]. Partials pushed to col-owner peers via st.async carrying
// mbarrier tx-completions; consumer expects 16KB/step. No per-step csync.
#define SM_P    0                  // ull P[32][512]          = 131072 B
#define SM_H    131072             // ull h2[2][32][8]        = 4096 B
#define SM_RED  135168             // float red[2][8][8][64]  = 32768 B
#define SM_BAR  167936             // ull full[2]             = 16 B
#define SM_TOT  167968

__global__ void __cluster_dims__(8,1,1) __launch_bounds__(256,1)
scan_kernel(const float* __restrict__ Uf, const float* __restrict__ Ub,
            float* __restrict__ out)
{
    extern __shared__ __align__(16) char smem[];
    ull*   P   = (ull*)(smem + SM_P);
    ull*   h2  = (ull*)(smem + SM_H);
    float* red = (float*)(smem + SM_RED);

    const unsigned rank = ctarank();
    const int cid = blockIdx.x >> 3;
    const int dir = cid >> 3;
    const int b0  = (cid & 7) * 8;
    const float* __restrict__ U = dir ? Ub : Uf;
    const int tid = threadIdx.x;
    const int k0 = (int)rank * 64;
    const unsigned sbase = s2u(smem);

    // one-time: pack own U k-slice as k-pairs, [kp][col]
    for (int i = tid; i < 32 * 512; i += 256) {
        const int kp = i >> 9, j = i & 511;
        const float u0 = U[(size_t)(k0 + 2 * kp) * 512 + j];
        const float u1 = U[(size_t)(k0 + 2 * kp + 1) * 512 + j];
        P[kp * 512 + j] = pk(u0, u1);
    }
    if (tid < 256) h2[tid] = 0ull;          // buffer 0
    if (tid == 0) { bar_init(sbase + SM_BAR, 1); bar_init(sbase + SM_BAR + 8, 1); }

    // compute role: cols c0, c0+1; peer = warp id
    const int c0 = 2 * tid;
    const unsigned peer = (unsigned)(tid >> 5);
    const unsigned pred = mapa_r(sbase + (unsigned)SM_RED, peer);
    const unsigned pbar0 = mapa_r(sbase + (unsigned)SM_BAR, peer);
    const unsigned pbar1 = pbar0 + 8u;

    // reduce role: row rr, local col pair lc
    const int rr = tid >> 5;
    const int lc = (tid & 31) * 2;
    const int jglob = (int)rank * 64 + lc;
    float* xwp = out + (((size_t)(b0 + rr) << 9)) * 1024 + (size_t)(dir << 9) + jglob;
    const int hidx = (tid & 31) * 8 + rr;

    csync();   // barriers + h2 + P visible cluster-wide

    for (int s = 0; s < 512; s++) {
        const int buf = s & 1;
        const unsigned lbar = sbase + (unsigned)SM_BAR + (unsigned)(buf * 8);
        if (tid == 0) bar_expect(lbar, 16384);

        const float2 xv = *(const float2*)(xwp + (size_t)s * 1024);  // prefetch

        ull acc0[8], acc1[8];
#pragma unroll
        for (int r = 0; r < 8; r++) { acc0[r] = 0ull; acc1[r] = 0ull; }

        const ull* hc = h2 + buf * 256;
#pragma unroll 4
        for (int kp = 0; kp < 32; kp++) {
            ull hp[8];
#pragma unroll
            for (int q = 0; q < 4; q++)
                *(uint4*)&hp[q * 2] = *(const uint4*)&hc[kp * 8 + q * 2];
            ull uu[2];
            *(uint4*)uu = *(const uint4*)&P[kp * 512 + c0];
#pragma unroll
            for (int r = 0; r < 8; r++) {
                acc0[r] = fma2(hp[r], uu[0], acc0[r]);
                acc1[r] = fma2(hp[r], uu[1], acc1[r]);
            }
        }

        // push partials to col-owner peer: red[buf][src=rank][r][c0&63]
        const unsigned dst = pred + (unsigned)(buf * 16384 + (int)rank * 2048 + (c0 & 63) * 4);
        const unsigned rbar = buf ? pbar1 : pbar0;
#pragma unroll
        for (int r = 0; r < 8; r++) {
            float a, b, p0, p1;
            upk(acc0[r], a, b); p0 = a + b;
            upk(acc1[r], a, b); p1 = a + b;
            st_async64(dst + (unsigned)(r * 256), pk(p0, p1), rbar);
        }

        bar_wait(lbar, (unsigned)((s >> 1) & 1));

        // reduce own slice: sum 8 srcs + xw, tanh
        const float* rp = red + buf * 4096 + rr * 64 + lc;
        float s0 = xv.x, s1 = xv.y;
#pragma unroll
        for (int q = 0; q < 8; q++) {
            const float2 v = *(const float2*)(rp + q * 512);
            s0 += v.x; s1 += v.y;
        }
        const float y0 = tanh_fast(s0), y1 = tanh_fast(s1);
        float2 w; w.x = y0; w.y = y1;
        *(float2*)(xwp + (size_t)s * 1024) = w;
        h2[(buf ^ 1) * 256 + hidx] = pk(y0, y1);
        __syncthreads();
    }
    csync();   // no CTA exits while peers may still push into its smem
}

extern "C" void kernel_launch(void* const* d_in, const int* in_sizes, int n_in,
                              void* d_out, int out_size) {
    const float* x  = (const float*)d_in[0];
    const float* Wf = (const float*)d_in[1];
    const float* Uf = (const float*)d_in[2];
    const float* bf = (const float*)d_in[3];
    const float* Wb = (const float*)d_in[4];
    const float* Ub = (const float*)d_in[5];
    const float* bb = (const float*)d_in[6];
    float* out = (float*)d_out;
    (void)in_sizes; (void)n_in; (void)out_size;

    dim3 gA(256, 4, 2);
    input_proj_kernel<<<gA, 256>>>(x, Wf, bf, Wb, bb, out);

    cudaFuncSetAttribute(scan_kernel,
                         cudaFuncAttributeMaxDynamicSharedMemorySize, SM_TOT);
    scan_kernel<<<128, 256, SM_TOT>>>(Uf, Ub, out);
}

// round 10
// speedup vs baseline: 2.8169x; 1.0013x over previous
#include <cuda_runtime.h>
#include <cstdint>
#include <math.h>

typedef unsigned long long ull;

__device__ __forceinline__ ull fma2(ull a, ull b, ull c) { ull d; asm("fma.rn.f32x2 %0,%1,%2,%3;":"=l"(d):"l"(a),"l"(b),"l"(c)); return d; }
__device__ __forceinline__ ull pk(float lo, float hi) { ull d; asm("mov.b64 %0,{%1,%2};":"=l"(d):"f"(lo),"f"(hi)); return d; }
__device__ __forceinline__ void upk(ull v, float& lo, float& hi) { asm("mov.b64 {%0,%1},%2;":"=f"(lo),"=f"(hi):"l"(v)); }
__device__ __forceinline__ unsigned s2u(const void* p){ unsigned r; asm("{.reg .u64 t; cvta.to.shared.u64 t, %1; cvt.u32.u64 %0, t;}":"=r"(r):"l"(p)); return r; }
__device__ __forceinline__ unsigned mapa_r(unsigned a, unsigned r){ unsigned o; asm("mapa.shared::cluster.u32 %0,%1,%2;":"=r"(o):"r"(a),"r"(r)); return o; }
__device__ __forceinline__ unsigned ctarank(){ unsigned r; asm("mov.u32 %0, %%cluster_ctarank;":"=r"(r)); return r; }
__device__ __forceinline__ void csync(){
    asm volatile("barrier.cluster.arrive.aligned;":::"memory");
    asm volatile("barrier.cluster.wait.aligned;":::"memory");
}
__device__ __forceinline__ void bar_init(unsigned bar, unsigned cnt){
    asm volatile("mbarrier.init.shared.b64 [%0], %1;" :: "r"(bar), "r"(cnt) : "memory");
}
__device__ __forceinline__ void bar_expect(unsigned bar, unsigned bytes){
    asm volatile("mbarrier.arrive.expect_tx.shared.b64 _, [%0], %1;" :: "r"(bar), "r"(bytes) : "memory");
}
__device__ __forceinline__ void bar_wait(unsigned bar, unsigned phase){
    unsigned done;
    asm volatile("{\n\t.reg .pred p;\n\t"
        "mbarrier.try_wait.parity.acquire.cta.shared::cta.b64 p, [%1], %2;\n\t"
        "selp.b32 %0, 1, 0, p;\n\t}"
        : "=r"(done) : "r"(bar), "r"(phase) : "memory");
    if (!done) {
        asm volatile("{\n\t.reg .pred P1;\n\t"
            "W_%=:\n\t"
            "mbarrier.try_wait.parity.acquire.cta.shared::cta.b64 P1, [%0], %1, 0x989680;\n\t"
            "@P1 bra.uni D_%=;\n\t"
            "bra.uni W_%=;\n\t"
            "D_%=:\n\t}"
            :: "r"(bar), "r"(phase) : "memory");
    }
}
__device__ __forceinline__ void fence_async(){
    asm volatile("fence.proxy.async.shared::cta;":::"memory");
}
// bulk DSMEM copy: local smem -> peer smem, completion on peer's mbarrier
__device__ __forceinline__ void blkcp_cluster(unsigned dst, unsigned src, unsigned bytes, unsigned rbar){
    asm volatile("cp.async.bulk.shared::cluster.shared::cta.mbarrier::complete_tx::bytes [%0], [%1], %2, [%3];"
        :: "r"(dst), "r"(src), "r"(bytes), "r"(rbar) : "memory");
}
__device__ __forceinline__ float tanh_fast(float x){
    float y; asm("tanh.approx.f32 %0, %1;" : "=f"(y) : "f"(x)); return y;
}

// ---------------- Phase A: xw = x @ W + b (f32x2, 128x128 tiles) -----------
// dir 0 -> out[b][t][j],  dir 1 -> out[b][511-t][512+j]
__global__ __launch_bounds__(256,2) void input_proj_kernel(
    const float* __restrict__ x,
    const float* __restrict__ Wf, const float* __restrict__ bf,
    const float* __restrict__ Wb, const float* __restrict__ bb,
    float* __restrict__ out)
{
    const int dir = blockIdx.z;
    const float* __restrict__ W = dir ? Wb : Wf;
    const float* __restrict__ bias = dir ? bb : bf;
    const int mBlk = blockIdx.x * 128;
    const int nBlk = blockIdx.y * 128;
    const int tid = threadIdx.x;

    __shared__ __align__(16) ull   As2[16][128];
    __shared__ __align__(16) float Bs[16][132];

    const int ar = tid >> 1, ac = (tid & 1) * 8;
    const int brow = tid >> 5, bcol = (tid & 31) * 4;
    const int tm = (tid >> 4) * 8, tn = (tid & 15) * 8;

    ull acc[8][4];
#pragma unroll
    for (int i = 0; i < 8; i++)
#pragma unroll
        for (int j = 0; j < 4; j++) acc[i][j] = 0ull;

    const float* aptr = x + (size_t)(mBlk + ar) * 512 + ac;
    const float* bptr = W + (size_t)brow * 512 + nBlk + bcol;

    for (int kk = 0; kk < 512; kk += 16) {
        const float4 av0 = *(const float4*)(aptr + kk);
        const float4 av1 = *(const float4*)(aptr + kk + 4);
        const float4 bv0 = *(const float4*)(bptr + (size_t)kk * 512);
        const float4 bv1 = *(const float4*)(bptr + (size_t)(kk + 8) * 512);
        __syncthreads();
        As2[ac + 0][ar] = pk(av0.x, av0.x);
        As2[ac + 1][ar] = pk(av0.y, av0.y);
        As2[ac + 2][ar] = pk(av0.z, av0.z);
        As2[ac + 3][ar] = pk(av0.w, av0.w);
        As2[ac + 4][ar] = pk(av1.x, av1.x);
        As2[ac + 5][ar] = pk(av1.y, av1.y);
        As2[ac + 6][ar] = pk(av1.z, av1.z);
        As2[ac + 7][ar] = pk(av1.w, av1.w);
        *(float4*)&Bs[brow][bcol]     = bv0;
        *(float4*)&Bs[brow + 8][bcol] = bv1;
        __syncthreads();
#pragma unroll
        for (int k = 0; k < 16; k++) {
            ull a2[8], b2[4];
#pragma unroll
            for (int u = 0; u < 4; u++)
                *(uint4*)&a2[u * 2] = *(const uint4*)&As2[k][tm + u * 2];
            *(uint4*)&b2[0] = *(const uint4*)&Bs[k][tn];
            *(uint4*)&b2[2] = *(const uint4*)&Bs[k][tn + 4];
#pragma unroll
            for (int i = 0; i < 8; i++)
#pragma unroll
                for (int j = 0; j < 4; j++)
                    acc[i][j] = fma2(a2[i], b2[j], acc[i][j]);
        }
    }

    float bo[8];
#pragma unroll
    for (int j = 0; j < 8; j++) bo[j] = bias[nBlk + tn + j];

#pragma unroll
    for (int i = 0; i < 8; i++) {
        const int m = mBlk + tm + i;
        const int b = m >> 9, t = m & 511;
        size_t addr;
        if (dir == 0) addr = (size_t)m * 1024 + (nBlk + tn);
        else          addr = ((size_t)(b << 9) + (511 - t)) * 1024 + 512 + (nBlk + tn);
        float v[8];
#pragma unroll
        for (int j = 0; j < 4; j++) {
            float lo, hi; upk(acc[i][j], lo, hi);
            v[2 * j] = lo + bo[2 * j]; v[2 * j + 1] = hi + bo[2 * j + 1];
        }
        *(float4*)(out + addr)     = *(float4*)&v[0];
        *(float4*)(out + addr + 4) = *(float4*)&v[4];
    }
}

// ---------------- Phase B: k-sliced cluster scan, bulk-copy exchange -------
// 16 clusters x 8 CTAs x 256 thr. CTA rank owns U rows [64r,64r+64) packed as
// k-pairs P[kp][col]; own h slice double-buffered h2[buf][kp][row]. Each warp
// stages its 2KB partial slot locally, then ONE cp.async.bulk to peer (rank =
// warp id) carrying mbarrier tx-completion; consumer expects 16KB/step.
#define SM_P    0                  // ull P[32][512]          = 131072 B
#define SM_H    131072             // ull h2[2][32][8]        = 4096 B
#define SM_RED  135168             // float red[2][8][8][64]  = 32768 B
#define SM_STG  167936             // staging [2][8][2048]    = 32768 B
#define SM_BAR  200704             // ull full[2]             = 16 B
#define SM_TOT  200736

__global__ void __cluster_dims__(8,1,1) __launch_bounds__(256,1)
scan_kernel(const float* __restrict__ Uf, const float* __restrict__ Ub,
            float* __restrict__ out)
{
    extern __shared__ __align__(16) char smem[];
    ull*   P   = (ull*)(smem + SM_P);
    ull*   h2  = (ull*)(smem + SM_H);
    float* red = (float*)(smem + SM_RED);

    const unsigned rank = ctarank();
    const int cid = blockIdx.x >> 3;
    const int dir = cid >> 3;
    const int b0  = (cid & 7) * 8;
    const float* __restrict__ U = dir ? Ub : Uf;
    const int tid = threadIdx.x;
    const int k0 = (int)rank * 64;
    const unsigned sbase = s2u(smem);

    // one-time: pack own U k-slice as k-pairs, [kp][col]
    for (int i = tid; i < 32 * 512; i += 256) {
        const int kp = i >> 9, j = i & 511;
        const float u0 = U[(size_t)(k0 + 2 * kp) * 512 + j];
        const float u1 = U[(size_t)(k0 + 2 * kp + 1) * 512 + j];
        P[kp * 512 + j] = pk(u0, u1);
    }
    if (tid < 256) h2[tid] = 0ull;
    if (tid == 0) { bar_init(sbase + SM_BAR, 1); bar_init(sbase + SM_BAR + 8, 1); }

    // compute role: cols c0, c0+1; peer = warp id
    const int c0 = 2 * tid;
    const int lane2 = (tid & 31) * 2;            // col within 64-slot
    const unsigned peer = (unsigned)(tid >> 5);
    const unsigned predR = mapa_r(sbase + (unsigned)SM_RED, peer);
    const unsigned pbar  = mapa_r(sbase + (unsigned)SM_BAR, peer);
    // local staging slot for this warp
    const unsigned stg_w = sbase + (unsigned)SM_STG + (unsigned)((tid >> 5) * 2048);

    // reduce role: row rr, local col pair lc
    const int rr = tid >> 5;
    const int lc = (tid & 31) * 2;
    const int jglob = (int)rank * 64 + lc;
    float* xwp = out + (((size_t)(b0 + rr) << 9)) * 1024 + (size_t)(dir << 9) + jglob;
    const int hidx = (tid & 31) * 8 + rr;

    csync();   // barriers + h2 + P visible cluster-wide

    for (int s = 0; s < 512; s++) {
        const int buf = s & 1;
        const unsigned lbar = sbase + (unsigned)SM_BAR + (unsigned)(buf * 8);
        if (tid == 0) bar_expect(lbar, 16384);

        const float2 xv = *(const float2*)(xwp + (size_t)s * 1024);  // prefetch

        ull acc0[8], acc1[8];
#pragma unroll
        for (int r = 0; r < 8; r++) { acc0[r] = 0ull; acc1[r] = 0ull; }

        const ull* hc = h2 + buf * 256;
#pragma unroll 4
        for (int kp = 0; kp < 32; kp++) {
            ull hp[8];
#pragma unroll
            for (int q = 0; q < 4; q++)
                *(uint4*)&hp[q * 2] = *(const uint4*)&hc[kp * 8 + q * 2];
            ull uu[2];
            *(uint4*)uu = *(const uint4*)&P[kp * 512 + c0];
#pragma unroll
            for (int r = 0; r < 8; r++) {
                acc0[r] = fma2(hp[r], uu[0], acc0[r]);
                acc1[r] = fma2(hp[r], uu[1], acc1[r]);
            }
        }

        // stage partials locally in destination-slot layout [r][64 cols]
        const unsigned stg = stg_w + (unsigned)(buf * 16384);
#pragma unroll
        for (int r = 0; r < 8; r++) {
            float a, b, p0, p1;
            upk(acc0[r], a, b); p0 = a + b;
            upk(acc1[r], a, b); p1 = a + b;
            *(ull*)(smem + (stg - sbase) + (unsigned)(r * 256 + lane2 * 4)) = pk(p0, p1);
        }
        __syncwarp();
        if ((tid & 31) == 0) {
            fence_async();
            blkcp_cluster(predR + (unsigned)(buf * 16384 + (int)rank * 2048),
                          stg, 2048u, pbar + (unsigned)(buf * 8));
        }

        bar_wait(lbar, (unsigned)((s >> 1) & 1));

        // reduce own slice: sum 8 srcs + xw, tanh
        const float* rp = red + buf * 4096 + rr * 64 + lc;
        float s0 = xv.x, s1 = xv.y;
#pragma unroll
        for (int q = 0; q < 8; q++) {
            const float2 v = *(const float2*)(rp + q * 512);
            s0 += v.x; s1 += v.y;
        }
        const float y0 = tanh_fast(s0), y1 = tanh_fast(s1);
        float2 w; w.x = y0; w.y = y1;
        *(float2*)(xwp + (size_t)s * 1024) = w;
        h2[(buf ^ 1) * 256 + hidx] = pk(y0, y1);
        __syncthreads();
    }
    csync();   // no CTA exits while peers may still push into its smem
}

extern "C" void kernel_launch(void* const* d_in, const int* in_sizes, int n_in,
                              void* d_out, int out_size) {
    const float* x  = (const float*)d_in[0];
    const float* Wf = (const float*)d_in[1];
    const float* Uf = (const float*)d_in[2];
    const float* bf = (const float*)d_in[3];
    const float* Wb = (const float*)d_in[4];
    const float* Ub = (const float*)d_in[5];
    const float* bb = (const float*)d_in[6];
    float* out = (float*)d_out;
    (void)in_sizes; (void)n_in; (void)out_size;

    dim3 gA(256, 4, 2);
    input_proj_kernel<<<gA, 256>>>(x, Wf, bf, Wb, bb, out);

    cudaFuncSetAttribute(scan_kernel,
                         cudaFuncAttributeMaxDynamicSharedMemorySize, SM_TOT);
    scan_kernel<<<128, 256, SM_TOT>>>(Uf, Ub, out);
}